// round 6
// baseline (speedup 1.0000x reference)
#include <cuda_runtime.h>
#include <math_constants.h>

#define HID 128
#define FIN 3
#define NA  8
#define NN  32
#define NB  2048
#define GPB 16            // graphs per block (1 warp per graph in the tail)
#define THREADS 512
#define GRID (NB / GPB)   // 128
#define NCH 8             // K-chunks for the weight fold (1 warp each)
#define KCH (HID / NCH)   // 16

// Fully fused. Algebra: complete graph + self-loops => deg==32, norm==1/32 for
// every edge => GCN aggregation yields the SAME vector for every node of a
// graph; max-pool of identical vectors is that vector. No nonlinearity before
// W1, so fold:  Wz = (W_emb @ W_gcn) @ W1  (3x128),
//              bz = ((b_emb @ W_gcn) + b_gcn) @ W1 + b1.
// q[g] = leaky(mean_n(unary[g]) @ Wz + bz) . W2[:, argmax(actions[g])] + b2[am]
__global__ __launch_bounds__(THREADS, 1)
void fused_critic_kernel(const float* __restrict__ unary,     // [B, N, FIN]
                         const float* __restrict__ actions,   // [B, NA]
                         const float* __restrict__ W_emb,     // [FIN, HID]
                         const float* __restrict__ b_emb,     // [HID]
                         const float* __restrict__ W_gcn,     // [HID, HID]
                         const float* __restrict__ b_gcn,     // [HID]
                         const float* __restrict__ W1,        // [HID, HID]
                         const float* __restrict__ b1,        // [HID]
                         const float* __restrict__ W2,        // [HID, NA]
                         const float* __restrict__ b2,        // [NA]
                         float* __restrict__ out) {           // [B, 1]
    __shared__ float sWe[4][HID];          // W_emb rows + b_emb         (2 KB)
    __shared__ float sPart[NCH][4][HID];   // fold partials             (16 KB)
    __shared__ float sT[4][HID];           // T rows + bc                (2 KB)
    __shared__ float sWz[4][HID];          // Wz rows + bz               (2 KB)
    __shared__ float sW2t[NA * 129];       // W2^T, padded               (4 KB)
    __shared__ float sb2[NA];
    __shared__ float sbg[HID];             // b_gcn
    __shared__ float sb1[HID];             // b1
    __shared__ float su[GPB * NN * FIN];   // unary slab                 (6 KB)
    __shared__ float sM[GPB][3];           // per-graph means
    __shared__ int   sAI[GPB];             // per-graph argmax

    const int tid   = threadIdx.x;
    const int warp  = tid >> 5;
    const int lane  = tid & 31;
    const int gbase = blockIdx.x * GPB;
    const int j4    = lane * 4;            // 4 consecutive output columns
    const int k0    = warp * KCH;

    // ---- hoist W1 chunk into registers (independent of stage 1!) ----
    float4 w1v[KCH];
    if (warp < NCH) {
        #pragma unroll
        for (int kk = 0; kk < KCH; kk++)
            w1v[kk] = *(const float4*)(W1 + (k0 + kk) * HID + j4);   // LDG.128
    }

    // ---------------- staging (coalesced, front-batched) ----------------
    if (tid < FIN * HID)      ((float*)sWe)[tid] = W_emb[tid];
    else                      ((float*)sWe)[tid] = b_emb[tid - FIN * HID];
    if (tid < HID)            sbg[tid] = b_gcn[tid];
    else if (tid < 2 * HID)   sb1[tid - HID] = b1[tid - HID];
    #pragma unroll
    for (int i = tid; i < HID * NA; i += THREADS)
        sW2t[(i & 7) * 129 + (i >> 3)] = W2[i];
    if (tid < NA) sb2[tid] = b2[tid];
    if (tid < (GPB * NN * FIN) / 4)        // 384 float4
        ((float4*)su)[tid] = ((const float4*)(unary + (size_t)gbase * NN * FIN))[tid];
    __syncthreads();

    if (warp < NCH) {
        // ---------- fold stage 1: chunk of T = W_emb @ W_gcn ----------
        float4 a0 = {0,0,0,0}, a1 = {0,0,0,0}, a2 = {0,0,0,0}, ab = {0,0,0,0};
        #pragma unroll
        for (int kk = 0; kk < KCH; kk++) {
            const int k = k0 + kk;
            const float4 gv = *(const float4*)(W_gcn + k * HID + j4);  // LDG.128
            const float w0 = sWe[0][k], w1 = sWe[1][k], w2 = sWe[2][k], wb = sWe[3][k];
            a0.x = fmaf(w0, gv.x, a0.x); a0.y = fmaf(w0, gv.y, a0.y);
            a0.z = fmaf(w0, gv.z, a0.z); a0.w = fmaf(w0, gv.w, a0.w);
            a1.x = fmaf(w1, gv.x, a1.x); a1.y = fmaf(w1, gv.y, a1.y);
            a1.z = fmaf(w1, gv.z, a1.z); a1.w = fmaf(w1, gv.w, a1.w);
            a2.x = fmaf(w2, gv.x, a2.x); a2.y = fmaf(w2, gv.y, a2.y);
            a2.z = fmaf(w2, gv.z, a2.z); a2.w = fmaf(w2, gv.w, a2.w);
            ab.x = fmaf(wb, gv.x, ab.x); ab.y = fmaf(wb, gv.y, ab.y);
            ab.z = fmaf(wb, gv.z, ab.z); ab.w = fmaf(wb, gv.w, ab.w);
        }
        *(float4*)&sPart[warp][0][j4] = a0;
        *(float4*)&sPart[warp][1][j4] = a1;
        *(float4*)&sPart[warp][2][j4] = a2;
        *(float4*)&sPart[warp][3][j4] = ab;
        asm volatile("bar.sync 1, 256;" ::: "memory");   // fold warps only

        // ---------- warp-local reduce of OWN k-slice of T ----------
        {
            const int k  = k0 + (lane & 15);
            const int o1 = lane >> 4;        // 0/1
            const int o2 = o1 + 2;           // 2/3
            float s1 = 0.f, s2 = 0.f;
            #pragma unroll
            for (int cc = 0; cc < NCH; cc++) {
                s1 += sPart[cc][o1][k];
                s2 += sPart[cc][o2][k];
            }
            if (o2 == 3) s2 += sbg[k];       // bc row gets b_gcn
            sT[o1][k] = s1;
            sT[o2][k] = s2;
        }
        __syncwarp();

        // ---------- fold stage 2: chunk of Wz = T @ W1 (regs only) ----------
        a0 = make_float4(0,0,0,0); a1 = make_float4(0,0,0,0);
        a2 = make_float4(0,0,0,0); ab = make_float4(0,0,0,0);
        #pragma unroll
        for (int kk = 0; kk < KCH; kk++) {
            const int k = k0 + kk;
            const float4 wv = w1v[kk];                    // registers
            const float t0 = sT[0][k], t1 = sT[1][k], t2 = sT[2][k], tb = sT[3][k];
            a0.x = fmaf(t0, wv.x, a0.x); a0.y = fmaf(t0, wv.y, a0.y);
            a0.z = fmaf(t0, wv.z, a0.z); a0.w = fmaf(t0, wv.w, a0.w);
            a1.x = fmaf(t1, wv.x, a1.x); a1.y = fmaf(t1, wv.y, a1.y);
            a1.z = fmaf(t1, wv.z, a1.z); a1.w = fmaf(t1, wv.w, a1.w);
            a2.x = fmaf(t2, wv.x, a2.x); a2.y = fmaf(t2, wv.y, a2.y);
            a2.z = fmaf(t2, wv.z, a2.z); a2.w = fmaf(t2, wv.w, a2.w);
            ab.x = fmaf(tb, wv.x, ab.x); ab.y = fmaf(tb, wv.y, ab.y);
            ab.z = fmaf(tb, wv.z, ab.z); ab.w = fmaf(tb, wv.w, ab.w);
        }
        *(float4*)&sPart[warp][0][j4] = a0;
        *(float4*)&sPart[warp][1][j4] = a1;
        *(float4*)&sPart[warp][2][j4] = a2;
        *(float4*)&sPart[warp][3][j4] = ab;
        asm volatile("bar.sync 1, 256;" ::: "memory");   // fold warps only

        // ---------- final reduce: sWz (256 threads, 2 outputs each) ----------
        #pragma unroll
        for (int rpt = 0; rpt < 2; rpt++) {
            const int idx = tid + rpt * 256;
            const int o = idx >> 7, jj = idx & 127;
            float s = 0.f;
            #pragma unroll
            for (int cc = 0; cc < NCH; cc++) s += sPart[cc][o][jj];
            if (o == 3) s += sb1[jj];
            sWz[o][jj] = s;
        }
    } else {
        // ---------- overlapped: means + argmax (2 graphs per warp) ----------
        const float inv = 1.0f / (float)NN;
        #pragma unroll
        for (int p = 0; p < 2; p++) {
            const int t = (warp - NCH) * 2 + p;
            // mean over 32 nodes x 3 feats (stride-3 smem: conflict-free)
            float m0 = su[t * (NN * FIN) + lane * FIN + 0];
            float m1 = su[t * (NN * FIN) + lane * FIN + 1];
            float m2 = su[t * (NN * FIN) + lane * FIN + 2];
            #pragma unroll
            for (int off = 16; off; off >>= 1) {
                m0 += __shfl_xor_sync(0xffffffffu, m0, off);
                m1 += __shfl_xor_sync(0xffffffffu, m1, off);
                m2 += __shfl_xor_sync(0xffffffffu, m2, off);
            }
            // argmax over 8 actions (first-index tie-break == jnp.argmax)
            float av = (lane < NA) ? actions[(size_t)(gbase + t) * NA + lane]
                                   : -CUDART_INF_F;
            int ai = lane;
            #pragma unroll
            for (int off = 4; off; off >>= 1) {
                const float ov = __shfl_xor_sync(0xffffffffu, av, off);
                const int   oi = __shfl_xor_sync(0xffffffffu, ai, off);
                if (ov > av || (ov == av && oi < ai)) { av = ov; ai = oi; }
            }
            if (lane == 0) {
                sM[t][0] = m0 * inv; sM[t][1] = m1 * inv; sM[t][2] = m2 * inv;
                sAI[t] = ai;
            }
        }
    }
    __syncthreads();

    // ---------------- per-graph tail: hid + dot (warp == graph) ----------------
    const float m0 = sM[warp][0], m1 = sM[warp][1], m2 = sM[warp][2];
    const int   ai = sAI[warp];

    float q = 0.f;
    #pragma unroll
    for (int r = 0; r < 4; r++) {
        const int jj = lane + r * 32;
        float v = fmaf(m0, sWz[0][jj],
                  fmaf(m1, sWz[1][jj],
                  fmaf(m2, sWz[2][jj], sWz[3][jj])));
        v = v >= 0.f ? v : 0.01f * v;                      // LeakyReLU(0.01)
        q = fmaf(v, sW2t[ai * 129 + jj], q);
    }
    #pragma unroll
    for (int off = 16; off; off >>= 1)
        q += __shfl_xor_sync(0xffffffffu, q, off);

    if (lane == 0) out[gbase + warp] = q + sb2[ai];
}

extern "C" void kernel_launch(void* const* d_in, const int* in_sizes, int n_in,
                              void* d_out, int out_size) {
    // metadata order: unary, actions, W_emb, b_emb, W_gcn, b_gcn, W1, b1, W2, b2, src, dst
    const float* unary  = (const float*)d_in[0];
    const float* act    = (const float*)d_in[1];
    const float* W_emb  = (const float*)d_in[2];
    const float* b_emb  = (const float*)d_in[3];
    const float* W_gcn  = (const float*)d_in[4];
    const float* b_gcn  = (const float*)d_in[5];
    const float* W1     = (const float*)d_in[6];
    const float* b1     = (const float*)d_in[7];
    const float* W2     = (const float*)d_in[8];
    const float* b2     = (const float*)d_in[9];
    float* out = (float*)d_out;

    fused_critic_kernel<<<GRID, THREADS>>>(unary, act, W_emb, b_emb,
                                           W_gcn, b_gcn, W1, b1, W2, b2, out);
}

// round 8
// speedup vs baseline: 1.2878x; 1.2878x over previous
#include <cuda_runtime.h>
#include <math_constants.h>

#define HID 128
#define FIN 3
#define NA  8
#define NN  32
#define NB  2048
#define GPB 32            // graphs per block (1 warp per graph in the tail)
#define THREADS 1024
#define GRID (NB / GPB)   // 64
#define NCH 8             // K-chunks for the weight fold (warps 0..7)
#define KCH (HID / NCH)   // 16

__device__ __forceinline__ unsigned long long pk2(float lo, float hi) {
    unsigned long long r;
    asm("mov.b64 %0, {%1, %2};" : "=l"(r) : "f"(lo), "f"(hi));
    return r;
}
__device__ __forceinline__ unsigned long long ffma2(unsigned long long a,
                                                    unsigned long long b,
                                                    unsigned long long c) {
    unsigned long long d;
    asm("fma.rn.f32x2 %0, %1, %2, %3;" : "=l"(d) : "l"(a), "l"(b), "l"(c));
    return d;
}

// Fully fused. Algebra: complete graph + self-loops => deg==32, norm==1/32 for
// every edge => GCN aggregation is the SAME vector for every node of a graph;
// max-pool of identical vectors is that vector. No nonlinearity before W1:
//   Wz = (W_emb @ W_gcn) @ W1  (3x128),  bz = ((b_emb@W_gcn)+b_gcn)@W1 + b1
//   q[g] = leaky(mean_n(unary[g]) @ Wz + bz) . W2[:, argmax(act[g])] + b2[am]
__global__ __launch_bounds__(THREADS, 1)
void fused_critic_kernel(const float* __restrict__ unary,     // [B, N, FIN]
                         const float* __restrict__ actions,   // [B, NA]
                         const float* __restrict__ W_emb,     // [FIN, HID]
                         const float* __restrict__ b_emb,     // [HID]
                         const float* __restrict__ W_gcn,     // [HID, HID]
                         const float* __restrict__ b_gcn,     // [HID]
                         const float* __restrict__ W1,        // [HID, HID]
                         const float* __restrict__ b1,        // [HID]
                         const float* __restrict__ W2,        // [HID, NA]
                         const float* __restrict__ b2,        // [NA]
                         float* __restrict__ out) {           // [B, 1]
    __shared__ float sWe[4][HID];          // W_emb rows + b_emb     (2 KB)
    __shared__ float sPart[NCH][4][HID];   // fold partials         (16 KB)
    __shared__ float sT[4][HID];           // T rows + bc            (2 KB)
    __shared__ float sWz[4][HID];          // Wz rows + bz           (2 KB)
    __shared__ float sW2t[NA * 129];       // W2^T, padded           (4 KB)
    __shared__ float sb2[NA];
    __shared__ float sM[GPB][3];           // per-graph means
    __shared__ int   sAI[GPB];             // per-graph argmax

    const int tid   = threadIdx.x;
    const int warp  = tid >> 5;
    const int lane  = tid & 31;
    const int gbase = blockIdx.x * GPB;

    if (warp < NCH) {
        // ================= FOLD PATH (warps 0..7, 256 threads) =================
        const int j4 = lane * 4;
        const int k0 = warp * KCH;
        const int ft = warp * 32 + lane;          // 0..255

        // prefetch both weight tiles to L1 (no register cost)
        #pragma unroll
        for (int kk = 0; kk < KCH; kk++) {
            asm volatile("prefetch.global.L1 [%0];" ::
                         "l"(W_gcn + (k0 + kk) * HID + j4));
            asm volatile("prefetch.global.L1 [%0];" ::
                         "l"(W1 + (k0 + kk) * HID + j4));
        }
        // bias values needed later (issue loads early)
        const float bg  = b_gcn[k0 + (lane & 15)];
        const float b1r = b1[ft & 127];

        // stage sWe (512 floats, 2 per fold thread)
        {
            float* w = (float*)sWe;
            w[ft]       = (ft < FIN * HID) ? W_emb[ft] : b_emb[ft - FIN * HID];
            const int f2 = ft + 256;
            w[f2]       = (f2 < FIN * HID) ? W_emb[f2] : b_emb[f2 - FIN * HID];
        }
        asm volatile("bar.sync 1, 256;" ::: "memory");

        // ---- stage 1: chunk of T = W_emb @ W_gcn (f32x2, 2 cols/instr) ----
        unsigned long long A[4][2];
        #pragma unroll
        for (int r = 0; r < 4; r++) { A[r][0] = 0ull; A[r][1] = 0ull; }
        #pragma unroll
        for (int kk = 0; kk < KCH; kk++) {
            const int k = k0 + kk;
            const ulonglong2 gv = *(const ulonglong2*)(W_gcn + k * HID + j4);
            #pragma unroll
            for (int r = 0; r < 4; r++) {
                const unsigned long long wp = pk2(sWe[r][k], sWe[r][k]);
                A[r][0] = ffma2(wp, gv.x, A[r][0]);
                A[r][1] = ffma2(wp, gv.y, A[r][1]);
            }
        }
        #pragma unroll
        for (int r = 0; r < 4; r++)
            *(ulonglong2*)&sPart[warp][r][j4] = make_ulonglong2(A[r][0], A[r][1]);
        asm volatile("bar.sync 1, 256;" ::: "memory");

        // ---- warp-local reduce of OWN k-slice of T ----
        {
            const int k  = k0 + (lane & 15);
            const int o1 = lane >> 4;            // 0/1
            const int o2 = o1 + 2;               // 2/3
            float s1 = 0.f, s2 = 0.f;
            #pragma unroll
            for (int cc = 0; cc < NCH; cc++) {
                s1 += sPart[cc][o1][k];
                s2 += sPart[cc][o2][k];
            }
            if (o2 == 3) s2 += bg;               // bc row gets b_gcn
            sT[o1][k] = s1;
            sT[o2][k] = s2;
        }
        __syncwarp();

        // ---- stage 2: chunk of Wz = T @ W1 (W1 L1-hot from prefetch) ----
        #pragma unroll
        for (int r = 0; r < 4; r++) { A[r][0] = 0ull; A[r][1] = 0ull; }
        #pragma unroll
        for (int kk = 0; kk < KCH; kk++) {
            const int k = k0 + kk;
            const ulonglong2 wv = *(const ulonglong2*)(W1 + k * HID + j4);
            #pragma unroll
            for (int r = 0; r < 4; r++) {
                const unsigned long long tp = pk2(sT[r][k], sT[r][k]);
                A[r][0] = ffma2(tp, wv.x, A[r][0]);
                A[r][1] = ffma2(tp, wv.y, A[r][1]);
            }
        }
        #pragma unroll
        for (int r = 0; r < 4; r++)
            *(ulonglong2*)&sPart[warp][r][j4] = make_ulonglong2(A[r][0], A[r][1]);
        asm volatile("bar.sync 1, 256;" ::: "memory");

        // ---- final reduce: sWz (512 outputs, 2 per fold thread) ----
        #pragma unroll
        for (int rpt = 0; rpt < 2; rpt++) {
            const int idx = ft + rpt * 256;
            const int o = idx >> 7, jj = idx & 127;
            float s = 0.f;
            #pragma unroll
            for (int cc = 0; cc < NCH; cc++) s += sPart[cc][o][jj];
            if (o == 3) s += b1r;
            sWz[o][jj] = s;
        }
    } else {
        // ============ MEAN/ARGMAX PATH (warps 8..31) + W2 staging ============
        {   // stage sW2t / sb2 (768 threads cover 1024 elems)
            const int i = tid - 256;
            sW2t[(i & 7) * 129 + (i >> 3)] = W2[i];
            if (i < 256) {
                const int i2 = i + 768;
                sW2t[(i2 & 7) * 129 + (i2 >> 3)] = W2[i2];
            }
            if (i < NA) sb2[i] = b2[i];
        }
        const float inv = 1.0f / (float)NN;
        #pragma unroll
        for (int pass = 0; pass < 2; pass++) {
            if (pass == 1 && warp >= 16) break;
            const int t = (pass == 0) ? (warp - NCH) : (warp - NCH + 24);
            const float* ub = unary + (size_t)(gbase + t) * NN * FIN;
            // node features straight from global (12B/lane, 3 lines per LDG)
            float m0 = ub[lane * FIN + 0];
            float m1 = ub[lane * FIN + 1];
            float m2 = ub[lane * FIN + 2];
            #pragma unroll
            for (int off = 16; off; off >>= 1) {
                m0 += __shfl_xor_sync(0xffffffffu, m0, off);
                m1 += __shfl_xor_sync(0xffffffffu, m1, off);
                m2 += __shfl_xor_sync(0xffffffffu, m2, off);
            }
            // argmax over 8 actions (first-index tie-break == jnp.argmax)
            float av = (lane < NA) ? actions[(size_t)(gbase + t) * NA + lane]
                                   : -CUDART_INF_F;
            int ai = lane;
            #pragma unroll
            for (int off = 4; off; off >>= 1) {
                const float ov = __shfl_xor_sync(0xffffffffu, av, off);
                const int   oi = __shfl_xor_sync(0xffffffffu, ai, off);
                if (ov > av || (ov == av && oi < ai)) { av = ov; ai = oi; }
            }
            if (lane == 0) {
                sM[t][0] = m0 * inv; sM[t][1] = m1 * inv; sM[t][2] = m2 * inv;
                sAI[t] = ai;
            }
        }
    }
    __syncthreads();     // the ONLY block-wide barrier

    // ---------------- per-graph tail: hid + dot (warp == graph) ----------------
    const float m0 = sM[warp][0], m1 = sM[warp][1], m2 = sM[warp][2];
    const int   ai = sAI[warp];

    float q = 0.f;
    #pragma unroll
    for (int r = 0; r < 4; r++) {
        const int jj = lane + r * 32;
        float v = fmaf(m0, sWz[0][jj],
                  fmaf(m1, sWz[1][jj],
                  fmaf(m2, sWz[2][jj], sWz[3][jj])));
        v = v >= 0.f ? v : 0.01f * v;                      // LeakyReLU(0.01)
        q = fmaf(v, sW2t[ai * 129 + jj], q);
    }
    #pragma unroll
    for (int off = 16; off; off >>= 1)
        q += __shfl_xor_sync(0xffffffffu, q, off);

    if (lane == 0) out[gbase + warp] = q + sb2[ai];
}

extern "C" void kernel_launch(void* const* d_in, const int* in_sizes, int n_in,
                              void* d_out, int out_size) {
    // metadata order: unary, actions, W_emb, b_emb, W_gcn, b_gcn, W1, b1, W2, b2, src, dst
    const float* unary  = (const float*)d_in[0];
    const float* act    = (const float*)d_in[1];
    const float* W_emb  = (const float*)d_in[2];
    const float* b_emb  = (const float*)d_in[3];
    const float* W_gcn  = (const float*)d_in[4];
    const float* b_gcn  = (const float*)d_in[5];
    const float* W1     = (const float*)d_in[6];
    const float* b1     = (const float*)d_in[7];
    const float* W2     = (const float*)d_in[8];
    const float* b2     = (const float*)d_in[9];
    float* out = (float*)d_out;

    fused_critic_kernel<<<GRID, THREADS>>>(unary, act, W_emb, b_emb,
                                           W_gcn, b_gcn, W1, b1, W2, b2, out);
}